// round 10
// baseline (speedup 1.0000x reference)
#include <cuda_runtime.h>
#include <cstdint>

// Problem constants (fixed shapes per reference)
#define NSPANS 4096
#define TMAX   16
#define HDIM   768
#define H4     192          // HDIM / 4 (float4 lanes per row)
#define R4     576          // 3 * H4 = float4 per span repr (half output row)
#define NPAIRS 16384
#define SL     2048         // S * L
#define NENT   (2 * NPAIRS) // 32768 (pair, side) entries

// Scratch
__device__ float4 g_mean[NSPANS * H4];   // 12.6 MB mean vectors
__device__ int2   g_info[NSPANS];        // {first_off, last_off} f4 units
__device__ int    g_count[NSPANS];
__device__ int    g_cursor[NSPANS];
__device__ int    g_offset[NSPANS];
__device__ int    g_entries[NENT];       // packed p*2 + side

// ---------------------------------------------------------------- zero
__global__ void zero_kernel()
{
    const int i = blockIdx.x * 1024 + threadIdx.x;
    if (i < NSPANS) { g_count[i] = 0; g_cursor[i] = 0; }
}

// ---------------------------------------------------------------- reprs
// 2 spans per block (384 threads). Fully-unrolled clamped loop -> MLP 16.
__global__ __launch_bounds__(384) void reprs_kernel(
    const float* __restrict__ hidden,
    const int*   __restrict__ span_doc,
    const int*   __restrict__ span_tok,
    const int*   __restrict__ span_len)
{
    const int tid  = threadIdx.x;
    const int half = tid / H4;
    const int lane = tid - half * H4;
    const int n    = blockIdx.x * 2 + half;

    __shared__ int s_tok[2][TMAX];
    if (lane < TMAX)
        s_tok[half][lane] = __ldg(span_tok + n * TMAX + lane);
    __syncthreads();

    const int doc   = __ldg(span_doc + n);
    const int len   = __ldg(span_len + n);
    const int lenm1 = len - 1;

    const float4* __restrict__ base =
        reinterpret_cast<const float4*>(hidden) + (size_t)doc * SL * H4;

    float4 acc = make_float4(0.f, 0.f, 0.f, 0.f);

    #pragma unroll
    for (int t = 0; t < TMAX; ++t) {
        const int tt = (t < len) ? t : lenm1;
        const float w = (t < len) ? 1.0f : 0.0f;
        const float4 v = __ldg(base + (size_t)s_tok[half][tt] * H4 + lane);
        acc.x += v.x * w; acc.y += v.y * w;
        acc.z += v.z * w; acc.w += v.w * w;
    }

    const float inv = 1.0f / (float)len;
    g_mean[n * H4 + lane] = make_float4(acc.x * inv, acc.y * inv,
                                        acc.z * inv, acc.w * inv);

    if (lane == 0) {
        const int docbase = doc * SL;
        g_info[n] = make_int2((docbase + s_tok[half][0]) * H4,
                              (docbase + s_tok[half][lenm1]) * H4);
    }
}

// ---------------------------------------------------------------- count
__global__ void count_kernel(const int* __restrict__ pair_i,
                             const int* __restrict__ pair_j)
{
    const int e = blockIdx.x * 1024 + threadIdx.x;   // 0..NENT-1
    if (e >= NENT) return;
    const int p    = e >> 1;
    const int span = (e & 1) ? __ldg(pair_j + p) : __ldg(pair_i + p);
    atomicAdd(&g_count[span], 1);
}

// ---------------------------------------------------------------- scan
// Exclusive prefix sum of g_count[4096] -> g_offset. Single block, 1024 thr,
// 4 elements per thread + Hillis-Steele over thread sums.
__global__ __launch_bounds__(1024) void scan_kernel()
{
    const int t = threadIdx.x;
    int v0 = g_count[t * 4 + 0];
    int v1 = g_count[t * 4 + 1];
    int v2 = g_count[t * 4 + 2];
    int v3 = g_count[t * 4 + 3];
    const int s = v0 + v1 + v2 + v3;

    __shared__ int sh[1024];
    sh[t] = s;
    __syncthreads();
    #pragma unroll
    for (int d = 1; d < 1024; d <<= 1) {
        const int add = (t >= d) ? sh[t - d] : 0;
        __syncthreads();
        sh[t] += add;
        __syncthreads();
    }
    int ex = sh[t] - s;   // exclusive prefix of this thread's group

    g_offset[t * 4 + 0] = ex;           ex += v0;
    g_offset[t * 4 + 1] = ex;           ex += v1;
    g_offset[t * 4 + 2] = ex;           ex += v2;
    g_offset[t * 4 + 3] = ex;
}

// ---------------------------------------------------------------- fill
__global__ void fill_kernel(const int* __restrict__ pair_i,
                            const int* __restrict__ pair_j)
{
    const int e = blockIdx.x * 1024 + threadIdx.x;
    if (e >= NENT) return;
    const int p    = e >> 1;
    const int span = (e & 1) ? __ldg(pair_j + p) : __ldg(pair_i + p);
    const int pos  = g_offset[span] + atomicAdd(&g_cursor[span], 1);
    g_entries[pos] = e;
}

// ---------------------------------------------------------------- scatter
// One block of 576 threads per span. Each thread keeps exactly one float4 of
// the span repr [first|mean|last] in a register, then writes it to every
// (pair, side) occurrence: contiguous 9216-B half-row per iteration.
// Reads hit LTS once per span (37.7 MB total) instead of once per occurrence.
__global__ __launch_bounds__(576) void scatter_kernel(
    const float* __restrict__ hidden,
    float4*      __restrict__ out)
{
    const int n = blockIdx.x;
    const int t = threadIdx.x;        // 0..575

    const int2 ii = __ldg(&g_info[n]);
    const float4* __restrict__ hid4 = reinterpret_cast<const float4*>(hidden);

    float4 v;
    if (t < 192)       v = __ldg(hid4 + ii.x + t);              // first
    else if (t < 384)  v = __ldg(g_mean + n * H4 + (t - 192));  // mean
    else               v = __ldg(hid4 + ii.y + (t - 384));      // last

    const int start = g_offset[n];
    const int cnt   = g_count[n];

    for (int k = 0; k < cnt; ++k) {
        const int e = __ldg(&g_entries[start + k]);
        float4* __restrict__ dst =
            out + (size_t)(e >> 1) * 1152 + (e & 1) * R4 + t;
        __stcs(dst, v);
    }
}

extern "C" void kernel_launch(void* const* d_in, const int* in_sizes, int n_in,
                              void* d_out, int out_size)
{
    const float* hidden   = (const float*)d_in[0];
    const int*   span_doc = (const int*)  d_in[1];
    const int*   span_tok = (const int*)  d_in[2];
    const int*   span_len = (const int*)  d_in[3];
    const int*   pair_i   = (const int*)  d_in[4];
    const int*   pair_j   = (const int*)  d_in[5];
    float4*      out      = (float4*)     d_out;

    zero_kernel<<<(NSPANS + 1023) / 1024, 1024>>>();
    reprs_kernel<<<NSPANS / 2, 384>>>(hidden, span_doc, span_tok, span_len);
    count_kernel<<<NENT / 1024, 1024>>>(pair_i, pair_j);
    scan_kernel<<<1, 1024>>>();
    fill_kernel<<<NENT / 1024, 1024>>>(pair_i, pair_j);
    scatter_kernel<<<NSPANS, 576>>>(hidden, out);
}